// round 17
// baseline (speedup 1.0000x reference)
#include <cuda_runtime.h>

// out[r,c] = x[r,c] * scale[c],  scale[c] = (u[c] >= 0.1f) ? vec[c]/0.9f : 0
// x: [131072, 1024] fp32. DRAM-pinned stream (512 MB read + 512 MB write,
// ~6.8 TB/s / 85-86% DRAM = the chip's 1:1 R/W mix ceiling).
// FINAL config family — measured optimum on every axis:
//   single fused kernel (one graph node); float4 LDG.128 path; default cache
//   policy; 8 elems/thread, exact-fit grid; front-batch depth 4 (MLP=4);
//   multi-wave grid. This run: confirmation re-bench of the block=512 shape
//   (best observed total, 157.76us) vs block=256 (158.0-158.4, n=3).

#define DEPTH 1024
#define P_DROP 0.1f

__global__ void __launch_bounds__(512)
fused_scale8_mlp4_b512_kernel(const float4* __restrict__ x,
                              const float4* __restrict__ vec4,
                              const float4* __restrict__ u4,
                              float4* __restrict__ out) {
    int i = blockIdx.x * blockDim.x + threadIdx.x;
    const int S = gridDim.x * blockDim.x;   // 4,194,304 — multiple of 256

    // All 8 elements this thread touches share one column-quad.
    int c4 = i & (DEPTH / 4 - 1);
    float4 vv = __ldg(&vec4[c4]);           // 4 KB set: L1/L2 resident
    float4 uu = __ldg(&u4[c4]);
    const float r = 1.0f / (1.0f - P_DROP);
    float4 s;
    s.x = (uu.x >= P_DROP) ? vv.x * r : 0.0f;
    s.y = (uu.y >= P_DROP) ? vv.y * r : 0.0f;
    s.z = (uu.z >= P_DROP) ? vv.z * r : 0.0f;
    s.w = (uu.w >= P_DROP) ? vv.w * r : 0.0f;

    // Exact fit: 8 elements as two groups of 4 front-batched loads (MLP=4).
#pragma unroll
    for (int g = 0; g < 2; g++) {
        int b = i + g * 4 * S;
        float4 a0 = x[b];
        float4 a1 = x[b + S];
        float4 a2 = x[b + 2 * S];
        float4 a3 = x[b + 3 * S];
        a0.x *= s.x; a0.y *= s.y; a0.z *= s.z; a0.w *= s.w;
        a1.x *= s.x; a1.y *= s.y; a1.z *= s.z; a1.w *= s.w;
        a2.x *= s.x; a2.y *= s.y; a2.z *= s.z; a2.w *= s.w;
        a3.x *= s.x; a3.y *= s.y; a3.z *= s.z; a3.w *= s.w;
        out[b]         = a0;
        out[b + S]     = a1;
        out[b + 2 * S] = a2;
        out[b + 3 * S] = a3;
    }
}

extern "C" void kernel_launch(void* const* d_in, const int* in_sizes, int n_in,
                              void* d_out, int out_size) {
    const float* x   = (const float*)d_in[0];
    const float* vec = (const float*)d_in[1];
    const float* u   = (const float*)d_in[2];
    float* out = (float*)d_out;

    // n4 = out_size/4 = 33,554,432; 8192 blocks * 512 threads * 8 = n4 exactly.
    fused_scale8_mlp4_b512_kernel<<<8192, 512>>>(
        (const float4*)x, (const float4*)vec, (const float4*)u, (float4*)out);
}